// round 1
// baseline (speedup 1.0000x reference)
#include <cuda_runtime.h>
#include <cstddef>

#define NN 100000
#define NE 1600000
#define C 128

// ---------------- scratch (device globals; no allocs allowed) ----------------
__device__ int   g_deg[NN];
__device__ int   g_ptr[NN + 1];
__device__ int   g_cursor[NN];
__device__ float g_invc[NN];
__device__ int   g_csr[NE];
__device__ float g_agg[(size_t)NN * C];
__device__ float g_h1 [(size_t)NN * C];
__device__ float g_h2 [(size_t)NN * C];

// ---------------- CSR build ----------------
__global__ void zero_deg_kernel() {
    int i = blockIdx.x * blockDim.x + threadIdx.x;
    if (i < NN) g_deg[i] = 0;
}

__global__ void count_kernel(const int* __restrict__ dst) {
    int e = blockIdx.x * blockDim.x + threadIdx.x;
    if (e < NE) atomicAdd(&g_deg[dst[e]], 1);
}

// single-block exclusive scan of g_deg -> g_ptr  (warp-shuffle based)
__global__ void scan_kernel() {
    __shared__ int warp_sums[32];
    __shared__ int s_carry;
    const int lane = threadIdx.x & 31;
    const int wid  = threadIdx.x >> 5;
    if (threadIdx.x == 0) s_carry = 0;
    __syncthreads();
    for (int base = 0; base < NN; base += 1024) {
        int i = base + threadIdx.x;
        int v = (i < NN) ? g_deg[i] : 0;
        int incl = v;
        #pragma unroll
        for (int o = 1; o < 32; o <<= 1) {
            int t = __shfl_up_sync(0xFFFFFFFFu, incl, o);
            if (lane >= o) incl += t;
        }
        if (lane == 31) warp_sums[wid] = incl;
        __syncthreads();
        if (wid == 0) {
            int ws = warp_sums[lane];
            int wincl = ws;
            #pragma unroll
            for (int o = 1; o < 32; o <<= 1) {
                int t = __shfl_up_sync(0xFFFFFFFFu, wincl, o);
                if (lane >= o) wincl += t;
            }
            warp_sums[lane] = wincl - ws;   // exclusive warp prefix
        }
        __syncthreads();
        int excl = s_carry + warp_sums[wid] + (incl - v);
        if (i < NN) g_ptr[i] = excl;
        __syncthreads();
        if (threadIdx.x == 1023) s_carry = excl + v;
        __syncthreads();
    }
    if (threadIdx.x == 0) g_ptr[NN] = s_carry;
}

__global__ void prep_kernel() {
    int i = blockIdx.x * blockDim.x + threadIdx.x;
    if (i < NN) {
        int d = g_deg[i];
        g_invc[i] = 1.0f / (float)(d < 1 ? 1 : d);
        g_cursor[i] = 0;
    }
}

__global__ void build_kernel(const int* __restrict__ src, const int* __restrict__ dst) {
    int e = blockIdx.x * blockDim.x + threadIdx.x;
    if (e < NE) {
        int d   = dst[e];
        int pos = atomicAdd(&g_cursor[d], 1);
        g_csr[g_ptr[d] + pos] = src[e];
    }
}

// ---------------- aggregation: warp per node, gather + register accumulate ----------------
__global__ void agg_kernel(const float* __restrict__ feat) {
    int gw = (blockIdx.x * blockDim.x + threadIdx.x) >> 5;
    if (gw >= NN) return;
    int lane = threadIdx.x & 31;
    int beg = g_ptr[gw], end = g_ptr[gw + 1];
    float4 acc = make_float4(0.f, 0.f, 0.f, 0.f);
    int e = beg;
    for (; e + 2 <= end; e += 2) {
        int s0 = g_csr[e], s1 = g_csr[e + 1];
        float4 v0 = *reinterpret_cast<const float4*>(feat + (size_t)s0 * C + lane * 4);
        float4 v1 = *reinterpret_cast<const float4*>(feat + (size_t)s1 * C + lane * 4);
        acc.x += v0.x; acc.y += v0.y; acc.z += v0.z; acc.w += v0.w;
        acc.x += v1.x; acc.y += v1.y; acc.z += v1.z; acc.w += v1.w;
    }
    if (e < end) {
        int s = g_csr[e];
        float4 v = *reinterpret_cast<const float4*>(feat + (size_t)s * C + lane * 4);
        acc.x += v.x; acc.y += v.y; acc.z += v.z; acc.w += v.w;
    }
    *reinterpret_cast<float4*>(g_agg + (size_t)gw * C + lane * 4) = acc;
}

// ---------------- fused GEMM ----------------
// LAYER: out = relu( (agg*invc) @ W1 + A2 @ W2 + bias )           (K = 256)
// !LAYER: out = alpha*(A1 @ W1 + bias) + (1-alpha)*xres           (K = 128)
template <bool LAYER>
__global__ __launch_bounds__(256, 2) void gemm_kernel(
    const float* __restrict__ A1, const float* __restrict__ A2,
    const float* __restrict__ W1, const float* __restrict__ W2,
    const float* __restrict__ bias, const float* __restrict__ xres,
    const float* __restrict__ alphaPtr, float* __restrict__ out)
{
    __shared__ float As[2][8][C];
    __shared__ float Bs[2][8][C];
    const int tid   = threadIdx.x;
    const int m0    = blockIdx.x * 128;
    const int row_t = tid >> 4;      // 0..15
    const int col_t = tid & 15;      // 0..15
    const int ar    = tid >> 1;      // 0..127  (A loader row)
    const int akq   = (tid & 1) * 4; // A loader k-quad
    const int bk    = tid >> 5;      // 0..7    (B loader k-row)
    const int bn    = (tid & 31) * 4;
    const int grow  = m0 + ar;
    const bool arow_ok = grow < NN;
    const float invc = (LAYER && arow_ok) ? g_invc[grow] : 1.0f;
    const int NT = LAYER ? 32 : 16;

    float acc[8][8];
    #pragma unroll
    for (int i = 0; i < 8; i++)
        #pragma unroll
        for (int j = 0; j < 8; j++) acc[i][j] = 0.f;

    // tile 0
    {
        float4 av = make_float4(0.f, 0.f, 0.f, 0.f);
        if (arow_ok) {
            av = *reinterpret_cast<const float4*>(A1 + (size_t)grow * C + akq);
            if (LAYER) { av.x *= invc; av.y *= invc; av.z *= invc; av.w *= invc; }
        }
        float4 bv = *reinterpret_cast<const float4*>(W1 + bk * C + bn);
        As[0][akq + 0][ar] = av.x; As[0][akq + 1][ar] = av.y;
        As[0][akq + 2][ar] = av.z; As[0][akq + 3][ar] = av.w;
        *reinterpret_cast<float4*>(&Bs[0][bk][bn]) = bv;
    }
    __syncthreads();

    int buf = 0;
    for (int t = 0; t < NT; t++) {
        float4 av2 = make_float4(0.f, 0.f, 0.f, 0.f), bv2 = make_float4(0.f, 0.f, 0.f, 0.f);
        if (t + 1 < NT) {
            int kg = (t + 1) * 8 + akq;
            if (arow_ok) {
                if (!LAYER || kg < C) {
                    av2 = *reinterpret_cast<const float4*>(A1 + (size_t)grow * C + kg);
                    if (LAYER) { av2.x *= invc; av2.y *= invc; av2.z *= invc; av2.w *= invc; }
                } else {
                    av2 = *reinterpret_cast<const float4*>(A2 + (size_t)grow * C + (kg - C));
                }
            }
            int kgb = (t + 1) * 8 + bk;
            const float* W = (!LAYER || kgb < C) ? W1 : W2;
            bv2 = *reinterpret_cast<const float4*>(W + (kgb & (C - 1)) * C + bn);
        }
        #pragma unroll
        for (int ks = 0; ks < 8; ks++) {
            float a[8], b[8];
            #pragma unroll
            for (int i = 0; i < 8; i++) a[i] = As[buf][ks][row_t * 8 + i];
            #pragma unroll
            for (int j = 0; j < 8; j++) b[j] = Bs[buf][ks][col_t * 8 + j];
            #pragma unroll
            for (int i = 0; i < 8; i++)
                #pragma unroll
                for (int j = 0; j < 8; j++) acc[i][j] += a[i] * b[j];
        }
        if (t + 1 < NT) {
            int nb = buf ^ 1;
            As[nb][akq + 0][ar] = av2.x; As[nb][akq + 1][ar] = av2.y;
            As[nb][akq + 2][ar] = av2.z; As[nb][akq + 3][ar] = av2.w;
            *reinterpret_cast<float4*>(&Bs[nb][bk][bn]) = bv2;
            __syncthreads();
            buf = nb;
        }
    }

    float al = 0.f, om = 0.f;
    if (!LAYER) { al = *alphaPtr; om = 1.0f - al; }
    #pragma unroll
    for (int i = 0; i < 8; i++) {
        int r = m0 + row_t * 8 + i;
        if (r < NN) {
            #pragma unroll
            for (int jj = 0; jj < 8; jj += 4) {
                int c = col_t * 8 + jj;
                float4 v;
                v.x = acc[i][jj + 0] + bias[c + 0];
                v.y = acc[i][jj + 1] + bias[c + 1];
                v.z = acc[i][jj + 2] + bias[c + 2];
                v.w = acc[i][jj + 3] + bias[c + 3];
                if (LAYER) {
                    v.x = fmaxf(v.x, 0.f); v.y = fmaxf(v.y, 0.f);
                    v.z = fmaxf(v.z, 0.f); v.w = fmaxf(v.w, 0.f);
                } else {
                    float4 xr = *reinterpret_cast<const float4*>(xres + (size_t)r * C + c);
                    v.x = al * v.x + om * xr.x; v.y = al * v.y + om * xr.y;
                    v.z = al * v.z + om * xr.z; v.w = al * v.w + om * xr.w;
                }
                *reinterpret_cast<float4*>(out + (size_t)r * C + c) = v;
            }
        }
    }
}

// ---------------- launch ----------------
extern "C" void kernel_launch(void* const* d_in, const int* in_sizes, int n_in,
                              void* d_out, int out_size)
{
    const float* x    = (const float*)d_in[0];
    const int*   ei   = (const int*)  d_in[1];
    const float* W1l  = (const float*)d_in[2];
    const float* b1   = (const float*)d_in[3];
    const float* W1r  = (const float*)d_in[4];
    const float* W2l  = (const float*)d_in[5];
    const float* b2   = (const float*)d_in[6];
    const float* W2r  = (const float*)d_in[7];
    const float* Wd   = (const float*)d_in[8];
    const float* bd   = (const float*)d_in[9];
    const float* alph = (const float*)d_in[10];
    float* out = (float*)d_out;

    const int* src = ei;
    const int* dst = ei + NE;

    float *agg, *h1, *h2;
    cudaGetSymbolAddress((void**)&agg, g_agg);
    cudaGetSymbolAddress((void**)&h1,  g_h1);
    cudaGetSymbolAddress((void**)&h2,  g_h2);

    const int TB = 256;
    const int gN  = (NN + TB - 1) / TB;       // 391
    const int gE  = (NE + TB - 1) / TB;       // 6250
    const int gAg = (NN * 32 + TB - 1) / TB;  // 12500
    const int gM  = (NN + 127) / 128;         // 782

    // CSR build
    zero_deg_kernel<<<gN, TB>>>();
    count_kernel<<<gE, TB>>>(dst);
    scan_kernel<<<1, 1024>>>();
    prep_kernel<<<gN, TB>>>();
    build_kernel<<<gE, TB>>>(src, dst);

    // layer 1
    agg_kernel<<<gAg, TB>>>(x);
    gemm_kernel<true><<<gM, TB>>>(agg, x, W1l, W1r, b1, nullptr, nullptr, h1);
    // layer 2
    agg_kernel<<<gAg, TB>>>(h1);
    gemm_kernel<true><<<gM, TB>>>(agg, h1, W2l, W2r, b2, nullptr, nullptr, h2);
    // decoder + residual blend
    gemm_kernel<false><<<gM, TB>>>(h2, nullptr, Wd, nullptr, bd, x, alph, out);

    (void)in_sizes; (void)n_in; (void)out_size;
}

// round 3
// speedup vs baseline: 1.3590x; 1.3590x over previous
#include <cuda_runtime.h>
#include <cuda_bf16.h>
#include <cstdint>
#include <cstddef>

#define NN 100000
#define NPAD 100096   // 782 * 128
#define NE 1600000
#define C 128

// ---------------- scratch (device globals; zero-initialized at load) ----------------
__device__ int   g_deg[NN];
__device__ int   g_ptr[NN + 1];
__device__ int   g_cursor[NN];
__device__ float g_invc[NN];
__device__ int   g_csr[NE];
__device__ float g_h1f[(size_t)NN * C];

__device__ __nv_bfloat16 g_xh [(size_t)NPAD * C];
__device__ __nv_bfloat16 g_xl [(size_t)NPAD * C];
__device__ __nv_bfloat16 g_aggh[(size_t)NPAD * C];
__device__ __nv_bfloat16 g_aggl[(size_t)NPAD * C];
__device__ __nv_bfloat16 g_h1h[(size_t)NPAD * C];
__device__ __nv_bfloat16 g_h1l[(size_t)NPAD * C];
__device__ __nv_bfloat16 g_h2h[(size_t)NPAD * C];
__device__ __nv_bfloat16 g_h2l[(size_t)NPAD * C];

__device__ __nv_bfloat16 g_w1h[128 * 256], g_w1l[128 * 256];
__device__ __nv_bfloat16 g_w2h[128 * 256], g_w2l[128 * 256];
__device__ __nv_bfloat16 g_wdh[128 * 128], g_wdl[128 * 128];

// ---------------- helpers ----------------
__device__ __forceinline__ uint32_t s2u(const void* p) {
    uint32_t a;
    asm("{ .reg .u64 t; cvta.to.shared.u64 t, %1; cvt.u32.u64 %0, t; }" : "=r"(a) : "l"(p));
    return a;
}
__device__ __forceinline__ void split1(float v, __nv_bfloat16& h, __nv_bfloat16& l) {
    h = __float2bfloat16(v);
    l = __float2bfloat16(v - __bfloat162float(h));
}
__device__ __forceinline__ void ldsm4(uint32_t* r, uint32_t addr) {
    asm volatile("ldmatrix.sync.aligned.m8n8.x4.shared.b16 {%0,%1,%2,%3}, [%4];"
                 : "=r"(r[0]), "=r"(r[1]), "=r"(r[2]), "=r"(r[3]) : "r"(addr));
}
__device__ __forceinline__ void mma16816(float* d, const uint32_t* a, const uint32_t* b) {
    asm volatile(
        "mma.sync.aligned.m16n8k16.row.col.f32.bf16.bf16.f32 "
        "{%0,%1,%2,%3}, {%4,%5,%6,%7}, {%8,%9}, {%0,%1,%2,%3};"
        : "+f"(d[0]), "+f"(d[1]), "+f"(d[2]), "+f"(d[3])
        : "r"(a[0]), "r"(a[1]), "r"(a[2]), "r"(a[3]), "r"(b[0]), "r"(b[1]));
}
__device__ __forceinline__ uint32_t sw128(uint32_t off) {
    return off ^ ((off >> 3) & 0x70u);
}

// ---------------- CSR build ----------------
__global__ void zero_deg_kernel() {
    int i = blockIdx.x * blockDim.x + threadIdx.x;
    if (i < NN) g_deg[i] = 0;
}
__global__ void count_kernel(const int* __restrict__ dst) {
    int e = blockIdx.x * blockDim.x + threadIdx.x;
    if (e < NE) atomicAdd(&g_deg[dst[e]], 1);
}
__global__ void scan_kernel() {
    __shared__ int warp_sums[32];
    __shared__ int s_carry;
    const int lane = threadIdx.x & 31;
    const int wid  = threadIdx.x >> 5;
    if (threadIdx.x == 0) s_carry = 0;
    __syncthreads();
    for (int base = 0; base < NN; base += 1024) {
        int i = base + threadIdx.x;
        int v = (i < NN) ? g_deg[i] : 0;
        int incl = v;
        #pragma unroll
        for (int o = 1; o < 32; o <<= 1) {
            int t = __shfl_up_sync(0xFFFFFFFFu, incl, o);
            if (lane >= o) incl += t;
        }
        if (lane == 31) warp_sums[wid] = incl;
        __syncthreads();
        if (wid == 0) {
            int ws = warp_sums[lane];
            int wincl = ws;
            #pragma unroll
            for (int o = 1; o < 32; o <<= 1) {
                int t = __shfl_up_sync(0xFFFFFFFFu, wincl, o);
                if (lane >= o) wincl += t;
            }
            warp_sums[lane] = wincl - ws;
        }
        __syncthreads();
        int excl = s_carry + warp_sums[wid] + (incl - v);
        if (i < NN) g_ptr[i] = excl;
        __syncthreads();
        if (threadIdx.x == 1023) s_carry = excl + v;
        __syncthreads();
    }
    if (threadIdx.x == 0) g_ptr[NN] = s_carry;
}
__global__ void prep_kernel() {
    int i = blockIdx.x * blockDim.x + threadIdx.x;
    if (i < NN) {
        int d = g_deg[i];
        g_invc[i] = 1.0f / (float)(d < 1 ? 1 : d);
        g_cursor[i] = 0;
    }
}
__global__ void build_kernel(const int* __restrict__ src, const int* __restrict__ dst) {
    int e = blockIdx.x * blockDim.x + threadIdx.x;
    if (e < NE) {
        int d   = dst[e];
        int pos = atomicAdd(&g_cursor[d], 1);
        g_csr[g_ptr[d] + pos] = src[e];
    }
}

// ---------------- fp32 -> (hi, lo) bf16 split for x ----------------
__global__ void split_kernel(const float* __restrict__ in,
                             __nv_bfloat16* __restrict__ hi,
                             __nv_bfloat16* __restrict__ lo) {
    int i = blockIdx.x * blockDim.x + threadIdx.x;
    if (i < NN * C / 4) {
        float4 v = ((const float4*)in)[i];
        __nv_bfloat162 h01, h23, l01, l23;
        split1(v.x, h01.x, l01.x); split1(v.y, h01.y, l01.y);
        split1(v.z, h23.x, l23.x); split1(v.w, h23.y, l23.y);
        ((__nv_bfloat162*)hi)[i * 2]     = h01;
        ((__nv_bfloat162*)hi)[i * 2 + 1] = h23;
        ((__nv_bfloat162*)lo)[i * 2]     = l01;
        ((__nv_bfloat162*)lo)[i * 2 + 1] = l23;
    }
}

// ---------------- weight prep: B[n][k] = W[k][n] transposed + split ----------------
__global__ void wprep_kernel(const float* __restrict__ Wl, const float* __restrict__ Wr,
                             __nv_bfloat16* __restrict__ bh, __nv_bfloat16* __restrict__ bl,
                             int K) {
    int n = blockIdx.x;
    for (int k = threadIdx.x; k < K; k += blockDim.x) {
        float v = (k < C) ? Wl[k * C + n] : Wr[(k - C) * C + n];
        __nv_bfloat16 h, l;
        split1(v, h, l);
        bh[n * K + k] = h;
        bl[n * K + k] = l;
    }
}

// ---------------- aggregation: warp per node, mean in fp32, write hi/lo bf16 ----------------
__global__ void agg_kernel(const float* __restrict__ feat) {
    int gw = (blockIdx.x * blockDim.x + threadIdx.x) >> 5;
    if (gw >= NN) return;
    int lane = threadIdx.x & 31;
    int beg = g_ptr[gw], end = g_ptr[gw + 1];
    float4 acc = make_float4(0.f, 0.f, 0.f, 0.f);
    int e = beg;
    for (; e + 2 <= end; e += 2) {
        int s0 = g_csr[e], s1 = g_csr[e + 1];
        float4 v0 = *reinterpret_cast<const float4*>(feat + (size_t)s0 * C + lane * 4);
        float4 v1 = *reinterpret_cast<const float4*>(feat + (size_t)s1 * C + lane * 4);
        acc.x += v0.x; acc.y += v0.y; acc.z += v0.z; acc.w += v0.w;
        acc.x += v1.x; acc.y += v1.y; acc.z += v1.z; acc.w += v1.w;
    }
    if (e < end) {
        int s = g_csr[e];
        float4 v = *reinterpret_cast<const float4*>(feat + (size_t)s * C + lane * 4);
        acc.x += v.x; acc.y += v.y; acc.z += v.z; acc.w += v.w;
    }
    float iv = g_invc[gw];
    acc.x *= iv; acc.y *= iv; acc.z *= iv; acc.w *= iv;
    __nv_bfloat162 h01, h23, l01, l23;
    split1(acc.x, h01.x, l01.x); split1(acc.y, h01.y, l01.y);
    split1(acc.z, h23.x, l23.x); split1(acc.w, h23.y, l23.y);
    size_t off = (size_t)gw * C + lane * 4;
    ((__nv_bfloat162*)(g_aggh + off))[0] = h01;
    ((__nv_bfloat162*)(g_aggh + off))[1] = h23;
    ((__nv_bfloat162*)(g_aggl + off))[0] = l01;
    ((__nv_bfloat162*)(g_aggl + off))[1] = l23;
}

// ---------------- mma.sync split-bf16 GEMM ----------------
// D[128, 128] = A[128, K] @ B^T  via (AhBh + AhBl + AlBh), fp32 accum.
// MODE 0: layer1 (K=256, relu, write f32 + hi/lo)
// MODE 1: layer2 (K=256, relu, write hi/lo only)
// MODE 2: decoder (K=128, blend with xres, write f32 out)
// SMEM: 4 tiles of [128 rows x 64 k-cols] bf16 = 16KB each (SW128 swizzled).
template <int MODE>
__global__ __launch_bounds__(256) void gemm_mma_kernel(
    const __nv_bfloat16* __restrict__ A1h, const __nv_bfloat16* __restrict__ A1l,
    const __nv_bfloat16* __restrict__ A2h, const __nv_bfloat16* __restrict__ A2l,
    const __nv_bfloat16* __restrict__ Bh,  const __nv_bfloat16* __restrict__ Bl,
    const float* __restrict__ bias, const float* __restrict__ xres,
    const float* __restrict__ alphaPtr,
    float* __restrict__ outF,
    __nv_bfloat16* __restrict__ outH, __nv_bfloat16* __restrict__ outL)
{
    constexpr int K   = (MODE == 2) ? 128 : 256;
    constexpr int NCH = K / 64;
    extern __shared__ __align__(128) char smem[];
    char* tAh = smem;
    char* tAl = smem + 16384;
    char* tBh = smem + 32768;
    char* tBl = smem + 49152;
    const uint32_t uAh = s2u(tAh), uAl = s2u(tAl), uBh = s2u(tBh), uBl = s2u(tBl);

    const int tid  = threadIdx.x;
    const int wid  = tid >> 5;
    const int lane = tid & 31;
    const int m0   = blockIdx.x * 128;
    const int m0w  = (wid >> 1) * 32;   // warp m offset (0,32,64,96)
    const int n0w  = (wid & 1) * 64;    // warp n offset (0,64)

    float acc[2][8][4];
    #pragma unroll
    for (int i = 0; i < 2; i++)
        #pragma unroll
        for (int j = 0; j < 8; j++)
            #pragma unroll
            for (int q = 0; q < 4; q++) acc[i][j][q] = 0.f;

    const int ldr  = tid >> 1;          // loader row 0..127
    const int ldc0 = (tid & 1) * 4;     // first 16B chunk (of 8 per row)

    for (int kc = 0; kc < NCH; kc++) {
        const __nv_bfloat16* sAh = (MODE != 2 && kc >= 2) ? A2h : A1h;
        const __nv_bfloat16* sAl = (MODE != 2 && kc >= 2) ? A2l : A1l;
        const int aoff = (MODE == 2) ? kc * 128 : (kc & 1) * 128;
        const char* pAh = (const char*)sAh + (size_t)(m0 + ldr) * 256 + aoff;
        const char* pAl = (const char*)sAl + (size_t)(m0 + ldr) * 256 + aoff;
        const char* pBh = (const char*)Bh + (size_t)ldr * (2 * K) + kc * 128;
        const char* pBl = (const char*)Bl + (size_t)ldr * (2 * K) + kc * 128;
        __syncthreads();
        #pragma unroll
        for (int i = 0; i < 4; i++) {
            const int c16 = ldc0 + i;
            const uint32_t sw = sw128((uint32_t)(ldr * 128 + c16 * 16));
            *(uint4*)(tAh + sw) = *(const uint4*)(pAh + c16 * 16);
            *(uint4*)(tAl + sw) = *(const uint4*)(pAl + c16 * 16);
            *(uint4*)(tBh + sw) = *(const uint4*)(pBh + c16 * 16);
            *(uint4*)(tBl + sw) = *(const uint4*)(pBl + c16 * 16);
        }
        __syncthreads();

        #pragma unroll
        for (int s = 0; s < 4; s++) {
            // A fragments (hi & lo): rows m0w + sub*16 + (lane&15), kbyte s*32 + (lane>>4)*16
            uint32_t aH[2][4], aL[2][4], bb[4][4];
            #pragma unroll
            for (int sub = 0; sub < 2; sub++) {
                const uint32_t off = sw128((uint32_t)(
                    (m0w + sub * 16 + (lane & 15)) * 128 + s * 32 + (lane >> 4) * 16));
                ldsm4(aH[sub], uAh + off);
                ldsm4(aL[sub], uAl + off);
            }
            // B hi fragments: n rows n0w + p*16 + (lane&7) + ((lane>>4)<<3), kbyte s*32 + ((lane>>3)&1)*16
            #pragma unroll
            for (int p = 0; p < 4; p++) {
                const uint32_t off = sw128((uint32_t)(
                    (n0w + p * 16 + (lane & 7) + ((lane >> 4) << 3)) * 128 +
                    s * 32 + ((lane >> 3) & 1) * 16));
                ldsm4(bb[p], uBh + off);
            }
            #pragma unroll
            for (int sub = 0; sub < 2; sub++)
                #pragma unroll
                for (int p = 0; p < 4; p++) {
                    mma16816(acc[sub][p * 2 + 0], aH[sub], &bb[p][0]);
                    mma16816(acc[sub][p * 2 + 1], aH[sub], &bb[p][2]);
                }
            #pragma unroll
            for (int sub = 0; sub < 2; sub++)
                #pragma unroll
                for (int p = 0; p < 4; p++) {
                    mma16816(acc[sub][p * 2 + 0], aL[sub], &bb[p][0]);
                    mma16816(acc[sub][p * 2 + 1], aL[sub], &bb[p][2]);
                }
            // B lo fragments (reuse bb), product Ah*Bl
            #pragma unroll
            for (int p = 0; p < 4; p++) {
                const uint32_t off = sw128((uint32_t)(
                    (n0w + p * 16 + (lane & 7) + ((lane >> 4) << 3)) * 128 +
                    s * 32 + ((lane >> 3) & 1) * 16));
                ldsm4(bb[p], uBl + off);
            }
            #pragma unroll
            for (int sub = 0; sub < 2; sub++)
                #pragma unroll
                for (int p = 0; p < 4; p++) {
                    mma16816(acc[sub][p * 2 + 0], aH[sub], &bb[p][0]);
                    mma16816(acc[sub][p * 2 + 1], aH[sub], &bb[p][2]);
                }
        }
    }

    // ---------------- epilogue ----------------
    float al = 0.f, om = 0.f;
    if (MODE == 2) { al = *alphaPtr; om = 1.0f - al; }
    const int ccol0 = n0w + (lane & 3) * 2;
    #pragma unroll
    for (int sub = 0; sub < 2; sub++) {
        const int rbase = m0 + m0w + sub * 16 + (lane >> 2);
        #pragma unroll
        for (int f = 0; f < 8; f++) {
            const int col = ccol0 + f * 8;
            const float bx = bias[col], by = bias[col + 1];
            #pragma unroll
            for (int half = 0; half < 2; half++) {
                const int r = rbase + half * 8;
                if (r >= NN) continue;
                float vx = acc[sub][f][half * 2 + 0] + bx;
                float vy = acc[sub][f][half * 2 + 1] + by;
                if (MODE < 2) {
                    vx = fmaxf(vx, 0.f); vy = fmaxf(vy, 0.f);
                    __nv_bfloat162 h2, l2;
                    split1(vx, h2.x, l2.x); split1(vy, h2.y, l2.y);
                    *(__nv_bfloat162*)(outH + (size_t)r * C + col) = h2;
                    *(__nv_bfloat162*)(outL + (size_t)r * C + col) = l2;
                    if (MODE == 0) {
                        float2 fv = make_float2(vx, vy);
                        *(float2*)(outF + (size_t)r * C + col) = fv;
                    }
                } else {
                    const float2 xr = *(const float2*)(xres + (size_t)r * C + col);
                    float2 fv;
                    fv.x = al * vx + om * xr.x;
                    fv.y = al * vy + om * xr.y;
                    *(float2*)(outF + (size_t)r * C + col) = fv;
                }
            }
        }
    }
}

// ---------------- launch ----------------
extern "C" void kernel_launch(void* const* d_in, const int* in_sizes, int n_in,
                              void* d_out, int out_size)
{
    const float* x    = (const float*)d_in[0];
    const int*   ei   = (const int*)  d_in[1];
    const float* W1l  = (const float*)d_in[2];
    const float* b1   = (const float*)d_in[3];
    const float* W1r  = (const float*)d_in[4];
    const float* W2l  = (const float*)d_in[5];
    const float* b2   = (const float*)d_in[6];
    const float* W2r  = (const float*)d_in[7];
    const float* Wd   = (const float*)d_in[8];
    const float* bd   = (const float*)d_in[9];
    const float* alph = (const float*)d_in[10];
    float* out = (float*)d_out;

    const int* src = ei;
    const int* dst = ei + NE;

    float *h1f;
    __nv_bfloat16 *xh, *xl, *aggh, *aggl, *h1h, *h1l, *h2h, *h2l;
    __nv_bfloat16 *w1h, *w1l, *w2h, *w2l, *wdh, *wdl;
    cudaGetSymbolAddress((void**)&h1f,  g_h1f);
    cudaGetSymbolAddress((void**)&xh,   g_xh);
    cudaGetSymbolAddress((void**)&xl,   g_xl);
    cudaGetSymbolAddress((void**)&aggh, g_aggh);
    cudaGetSymbolAddress((void**)&aggl, g_aggl);
    cudaGetSymbolAddress((void**)&h1h,  g_h1h);
    cudaGetSymbolAddress((void**)&h1l,  g_h1l);
    cudaGetSymbolAddress((void**)&h2h,  g_h2h);
    cudaGetSymbolAddress((void**)&h2l,  g_h2l);
    cudaGetSymbolAddress((void**)&w1h,  g_w1h);
    cudaGetSymbolAddress((void**)&w1l,  g_w1l);
    cudaGetSymbolAddress((void**)&w2h,  g_w2h);
    cudaGetSymbolAddress((void**)&w2l,  g_w2l);
    cudaGetSymbolAddress((void**)&wdh,  g_wdh);
    cudaGetSymbolAddress((void**)&wdl,  g_wdl);

    const int SMEM_GEMM = 4 * 16384;  // 64KB
    cudaFuncSetAttribute(gemm_mma_kernel<0>, cudaFuncAttributeMaxDynamicSharedMemorySize, SMEM_GEMM);
    cudaFuncSetAttribute(gemm_mma_kernel<1>, cudaFuncAttributeMaxDynamicSharedMemorySize, SMEM_GEMM);
    cudaFuncSetAttribute(gemm_mma_kernel<2>, cudaFuncAttributeMaxDynamicSharedMemorySize, SMEM_GEMM);

    const int TB = 256;
    const int gN  = (NN + TB - 1) / TB;
    const int gE  = (NE + TB - 1) / TB;
    const int gAg = (NN * 32 + TB - 1) / TB;
    const int gM  = (NN + 127) / 128;        // 782
    const int gS  = (NN * C / 4 + TB - 1) / TB;

    // CSR build
    zero_deg_kernel<<<gN, TB>>>();
    count_kernel<<<gE, TB>>>(dst);
    scan_kernel<<<1, 1024>>>();
    prep_kernel<<<gN, TB>>>();
    build_kernel<<<gE, TB>>>(src, dst);

    // conversions / weight prep
    split_kernel<<<gS, TB>>>(x, xh, xl);
    wprep_kernel<<<128, 256>>>(W1l, W1r, w1h, w1l, 256);
    wprep_kernel<<<128, 256>>>(W2l, W2r, w2h, w2l, 256);
    wprep_kernel<<<128, 256>>>(Wd, nullptr, wdh, wdl, 128);

    // layer 1
    agg_kernel<<<gAg, TB>>>(x);
    gemm_mma_kernel<0><<<gM, 256, SMEM_GEMM>>>(aggh, aggl, xh, xl, w1h, w1l,
                                               b1, nullptr, nullptr, h1f, h1h, h1l);
    // layer 2
    agg_kernel<<<gAg, TB>>>(h1f);
    gemm_mma_kernel<1><<<gM, 256, SMEM_GEMM>>>(aggh, aggl, h1h, h1l, w2h, w2l,
                                               b2, nullptr, nullptr, nullptr, h2h, h2l);
    // decoder + residual blend
    gemm_mma_kernel<2><<<gM, 256, SMEM_GEMM>>>(h2h, h2l, nullptr, nullptr, wdh, wdl,
                                               bd, x, alph, out, nullptr, nullptr);

    (void)in_sizes; (void)n_in; (void)out_size;
}

// round 4
// speedup vs baseline: 1.8218x; 1.3406x over previous
#include <cuda_runtime.h>
#include <cuda_bf16.h>
#include <cstdint>
#include <cstddef>

#define NN 100000
#define NPAD 100096   // 782 * 128
#define NE 1600000
#define C 128
#define NB_SCAN 98    // ceil(NN / 1024)

// ---------------- scratch (device globals; zero-initialized at load) ----------------
__device__ int   g_deg[NN];
__device__ int   g_ptr[NN + 1];
__device__ int   g_cursor[NN];
__device__ float g_invc[NN];
__device__ int   g_csr[NE];
__device__ int   g_bsum[128];
__device__ float g_h1f[(size_t)NN * C];

__device__ __nv_bfloat16 g_xh [(size_t)NPAD * C];
__device__ __nv_bfloat16 g_xl [(size_t)NPAD * C];
__device__ __nv_bfloat16 g_aggh[(size_t)NPAD * C];
__device__ __nv_bfloat16 g_aggl[(size_t)NPAD * C];
__device__ __nv_bfloat16 g_h1h[(size_t)NPAD * C];
__device__ __nv_bfloat16 g_h1l[(size_t)NPAD * C];
__device__ __nv_bfloat16 g_h2h[(size_t)NPAD * C];
__device__ __nv_bfloat16 g_h2l[(size_t)NPAD * C];

__device__ __nv_bfloat16 g_w1h[128 * 256], g_w1l[128 * 256];
__device__ __nv_bfloat16 g_w2h[128 * 256], g_w2l[128 * 256];
__device__ __nv_bfloat16 g_wdh[128 * 128], g_wdl[128 * 128];

// ---------------- helpers ----------------
__device__ __forceinline__ uint32_t s2u(const void* p) {
    uint32_t a;
    asm("{ .reg .u64 t; cvta.to.shared.u64 t, %1; cvt.u32.u64 %0, t; }" : "=r"(a) : "l"(p));
    return a;
}
__device__ __forceinline__ void split1(float v, __nv_bfloat16& h, __nv_bfloat16& l) {
    h = __float2bfloat16(v);
    l = __float2bfloat16(v - __bfloat162float(h));
}
__device__ __forceinline__ void ldsm4(uint32_t* r, uint32_t addr) {
    asm volatile("ldmatrix.sync.aligned.m8n8.x4.shared.b16 {%0,%1,%2,%3}, [%4];"
                 : "=r"(r[0]), "=r"(r[1]), "=r"(r[2]), "=r"(r[3]) : "r"(addr));
}
__device__ __forceinline__ void mma16816(float* d, const uint32_t* a, const uint32_t* b) {
    asm volatile(
        "mma.sync.aligned.m16n8k16.row.col.f32.bf16.bf16.f32 "
        "{%0,%1,%2,%3}, {%4,%5,%6,%7}, {%8,%9}, {%0,%1,%2,%3};"
        : "+f"(d[0]), "+f"(d[1]), "+f"(d[2]), "+f"(d[3])
        : "r"(a[0]), "r"(a[1]), "r"(a[2]), "r"(a[3]), "r"(b[0]), "r"(b[1]));
}
// swizzle for 64-byte rows (8-row atom): XOR 16B-chunk bits [5:4] with row bits [8:7]
__device__ __forceinline__ uint32_t swz64(uint32_t off) {
    return off ^ ((off >> 3) & 0x30u);
}
__device__ __forceinline__ void cp16(uint32_t saddr, const void* gaddr) {
    asm volatile("cp.async.cg.shared.global [%0], [%1], 16;" :: "r"(saddr), "l"(gaddr));
}

// ---------------- CSR build ----------------
__global__ void zero_deg_kernel() {
    int i = blockIdx.x * blockDim.x + threadIdx.x;
    if (i < NN) g_deg[i] = 0;
}
__global__ void count_kernel(const int* __restrict__ dst) {
    int e = blockIdx.x * blockDim.x + threadIdx.x;
    if (e < NE) atomicAdd(&g_deg[dst[e]], 1);
}
// pass 1: per-block exclusive scan of deg -> g_ptr, block totals -> g_bsum
__global__ void scan1_kernel() {
    __shared__ int wsum[32];
    const int lane = threadIdx.x & 31;
    const int wid  = threadIdx.x >> 5;
    int i = blockIdx.x * 1024 + threadIdx.x;
    int v = (i < NN) ? g_deg[i] : 0;
    int incl = v;
    #pragma unroll
    for (int o = 1; o < 32; o <<= 1) {
        int t = __shfl_up_sync(0xFFFFFFFFu, incl, o);
        if (lane >= o) incl += t;
    }
    if (lane == 31) wsum[wid] = incl;
    __syncthreads();
    if (wid == 0) {
        int ws = wsum[lane];
        int wi = ws;
        #pragma unroll
        for (int o = 1; o < 32; o <<= 1) {
            int t = __shfl_up_sync(0xFFFFFFFFu, wi, o);
            if (lane >= o) wi += t;
        }
        wsum[lane] = wi - ws;
    }
    __syncthreads();
    int excl = wsum[wid] + incl - v;
    if (i < NN) g_ptr[i] = excl;
    if (threadIdx.x == 1023) g_bsum[blockIdx.x] = excl + v;
}
// pass 2: exclusive scan of the 98 block sums (single block, 128 threads)
__global__ void scan2_kernel() {
    __shared__ int ws[4];
    const int t = threadIdx.x;
    const int lane = t & 31;
    const int wid  = t >> 5;
    int v = (t < NB_SCAN) ? g_bsum[t] : 0;
    int incl = v;
    #pragma unroll
    for (int o = 1; o < 32; o <<= 1) {
        int s = __shfl_up_sync(0xFFFFFFFFu, incl, o);
        if (lane >= o) incl += s;
    }
    if (lane == 31) ws[wid] = incl;
    __syncthreads();
    int add = 0;
    #pragma unroll
    for (int w = 0; w < 4; w++) if (w < wid) add += ws[w];
    int excl = add + incl - v;
    __syncthreads();
    if (t < NB_SCAN) g_bsum[t] = excl;
}
// pass 3: add block offsets; fused prep (invc, cursor, ptr[NN])
__global__ void scan3_kernel() {
    int i = blockIdx.x * 1024 + threadIdx.x;
    if (i == 0) g_ptr[NN] = NE;
    if (i < NN) {
        g_ptr[i] += g_bsum[blockIdx.x];
        int d = g_deg[i];
        g_invc[i] = 1.0f / (float)(d < 1 ? 1 : d);
        g_cursor[i] = 0;
    }
}
__global__ void build_kernel(const int* __restrict__ src, const int* __restrict__ dst) {
    int e = blockIdx.x * blockDim.x + threadIdx.x;
    if (e < NE) {
        int d   = dst[e];
        int pos = atomicAdd(&g_cursor[d], 1);
        g_csr[g_ptr[d] + pos] = src[e];
    }
}

// ---------------- fp32 -> (hi, lo) bf16 split for x ----------------
__global__ void split_kernel(const float* __restrict__ in,
                             __nv_bfloat16* __restrict__ hi,
                             __nv_bfloat16* __restrict__ lo) {
    int i = blockIdx.x * blockDim.x + threadIdx.x;
    if (i < NN * C / 4) {
        float4 v = ((const float4*)in)[i];
        __nv_bfloat162 h01, h23, l01, l23;
        split1(v.x, h01.x, l01.x); split1(v.y, h01.y, l01.y);
        split1(v.z, h23.x, l23.x); split1(v.w, h23.y, l23.y);
        ((__nv_bfloat162*)hi)[i * 2]     = h01;
        ((__nv_bfloat162*)hi)[i * 2 + 1] = h23;
        ((__nv_bfloat162*)lo)[i * 2]     = l01;
        ((__nv_bfloat162*)lo)[i * 2 + 1] = l23;
    }
}

// ---------------- weight prep (all 3 weight pairs in one launch; grid (128, 3)) ----------------
__global__ void wprep_kernel(const float* __restrict__ W1l, const float* __restrict__ W1r,
                             const float* __restrict__ W2l, const float* __restrict__ W2r,
                             const float* __restrict__ Wd) {
    const int n = blockIdx.x;
    const int which = blockIdx.y;
    const float* Wl; const float* Wr; __nv_bfloat16 *bh, *bl; int K;
    if (which == 0)      { Wl = W1l; Wr = W1r; bh = g_w1h; bl = g_w1l; K = 256; }
    else if (which == 1) { Wl = W2l; Wr = W2r; bh = g_w2h; bl = g_w2l; K = 256; }
    else                 { Wl = Wd;  Wr = nullptr; bh = g_wdh; bl = g_wdl; K = 128; }
    for (int k = threadIdx.x; k < K; k += blockDim.x) {
        float v = (k < C) ? Wl[k * C + n] : Wr[(k - C) * C + n];
        __nv_bfloat16 h, l;
        split1(v, h, l);
        bh[n * K + k] = h;
        bl[n * K + k] = l;
    }
}

// ---------------- aggregation: warp per node, 4-edge unrolled gather ----------------
__global__ void agg_kernel(const float* __restrict__ feat) {
    int gw = (blockIdx.x * blockDim.x + threadIdx.x) >> 5;
    if (gw >= NN) return;
    int lane = threadIdx.x & 31;
    int beg = g_ptr[gw], end = g_ptr[gw + 1];
    float4 acc = make_float4(0.f, 0.f, 0.f, 0.f);
    int e = beg;
    for (; e + 4 <= end; e += 4) {
        int s0 = g_csr[e], s1 = g_csr[e + 1], s2 = g_csr[e + 2], s3 = g_csr[e + 3];
        float4 v0 = *reinterpret_cast<const float4*>(feat + (size_t)s0 * C + lane * 4);
        float4 v1 = *reinterpret_cast<const float4*>(feat + (size_t)s1 * C + lane * 4);
        float4 v2 = *reinterpret_cast<const float4*>(feat + (size_t)s2 * C + lane * 4);
        float4 v3 = *reinterpret_cast<const float4*>(feat + (size_t)s3 * C + lane * 4);
        acc.x += v0.x + v1.x + v2.x + v3.x;
        acc.y += v0.y + v1.y + v2.y + v3.y;
        acc.z += v0.z + v1.z + v2.z + v3.z;
        acc.w += v0.w + v1.w + v2.w + v3.w;
    }
    for (; e < end; e++) {
        int s = g_csr[e];
        float4 v = *reinterpret_cast<const float4*>(feat + (size_t)s * C + lane * 4);
        acc.x += v.x; acc.y += v.y; acc.z += v.z; acc.w += v.w;
    }
    float iv = g_invc[gw];
    acc.x *= iv; acc.y *= iv; acc.z *= iv; acc.w *= iv;
    __nv_bfloat162 h01, h23, l01, l23;
    split1(acc.x, h01.x, l01.x); split1(acc.y, h01.y, l01.y);
    split1(acc.z, h23.x, l23.x); split1(acc.w, h23.y, l23.y);
    size_t off = (size_t)gw * C + lane * 4;
    ((__nv_bfloat162*)(g_aggh + off))[0] = h01;
    ((__nv_bfloat162*)(g_aggh + off))[1] = h23;
    ((__nv_bfloat162*)(g_aggl + off))[0] = l01;
    ((__nv_bfloat162*)(g_aggl + off))[1] = l23;
}

// ---------------- cp.async-pipelined split-bf16 GEMM ----------------
// D[128, 128] = A[128, K] @ B^T via (AhBh + AhBl + AlBh), fp32 accum.
// K consumed in 32-wide chunks; 2-stage double buffer (2 x 32KB).
// Stage layout: Ah[0,8K) Al[8K,16K) Bh[16K,24K) Bl[24K,32K); 64B rows, swz64.
// MODE 0: layer1 (K=256, relu, write f32 + hi/lo)
// MODE 1: layer2 (K=256, relu, write hi/lo)
// MODE 2: decoder (K=128, blend with xres, write f32)
template <int MODE>
__global__ __launch_bounds__(256) void gemm_mma_kernel(
    const __nv_bfloat16* __restrict__ A1h, const __nv_bfloat16* __restrict__ A1l,
    const __nv_bfloat16* __restrict__ A2h, const __nv_bfloat16* __restrict__ A2l,
    const __nv_bfloat16* __restrict__ Bh,  const __nv_bfloat16* __restrict__ Bl,
    const float* __restrict__ bias, const float* __restrict__ xres,
    const float* __restrict__ alphaPtr,
    float* __restrict__ outF,
    __nv_bfloat16* __restrict__ outH, __nv_bfloat16* __restrict__ outL)
{
    constexpr int K   = (MODE == 2) ? 128 : 256;
    constexpr int NCH = K / 32;
    extern __shared__ __align__(128) char smem[];
    const uint32_t us = s2u(smem);

    const int tid  = threadIdx.x;
    const int wid  = tid >> 5;
    const int lane = tid & 31;
    const int m0   = blockIdx.x * 128;
    const int m0w  = (wid >> 1) * 32;
    const int n0w  = (wid & 1) * 64;

    const int lrow = tid >> 1;          // loader row 0..127
    const int c16a = (tid & 1) * 2;     // loader 16B-chunk base (0 or 2)

    float acc[2][8][4];
    #pragma unroll
    for (int i = 0; i < 2; i++)
        #pragma unroll
        for (int j = 0; j < 8; j++)
            #pragma unroll
            for (int q = 0; q < 4; q++) acc[i][j][q] = 0.f;

    auto issue = [&](int kc, int buf) {
        const __nv_bfloat16* sAh = (MODE != 2 && kc >= NCH / 2) ? A2h : A1h;
        const __nv_bfloat16* sAl = (MODE != 2 && kc >= NCH / 2) ? A2l : A1l;
        const int aoff = (MODE == 2) ? kc * 64 : (kc & (NCH / 2 - 1)) * 64;
        const char* pAh = (const char*)sAh + (size_t)(m0 + lrow) * 256 + aoff;
        const char* pAl = (const char*)sAl + (size_t)(m0 + lrow) * 256 + aoff;
        const char* pBh = (const char*)Bh + (size_t)lrow * (2 * K) + kc * 64;
        const char* pBl = (const char*)Bl + (size_t)lrow * (2 * K) + kc * 64;
        const uint32_t sb = us + buf * 32768;
        #pragma unroll
        for (int j = 0; j < 2; j++) {
            const int c16 = c16a + j;
            const uint32_t so = swz64((uint32_t)(lrow * 64 + c16 * 16));
            cp16(sb + so,          pAh + c16 * 16);
            cp16(sb + 8192 + so,   pAl + c16 * 16);
            cp16(sb + 16384 + so,  pBh + c16 * 16);
            cp16(sb + 24576 + so,  pBl + c16 * 16);
        }
        asm volatile("cp.async.commit_group;" ::: "memory");
    };

    issue(0, 0);
    for (int kc = 0; kc < NCH; kc++) {
        if (kc + 1 < NCH) {
            issue(kc + 1, (kc + 1) & 1);
            asm volatile("cp.async.wait_group 1;" ::: "memory");
        } else {
            asm volatile("cp.async.wait_group 0;" ::: "memory");
        }
        __syncthreads();
        const uint32_t sb = us + (kc & 1) * 32768;
        #pragma unroll
        for (int s = 0; s < 2; s++) {
            uint32_t aH[2][4], aL[2][4], bb[4][4];
            #pragma unroll
            for (int sub = 0; sub < 2; sub++) {
                const uint32_t off = swz64((uint32_t)(
                    (m0w + sub * 16 + (lane & 15)) * 64 + s * 32 + (lane >> 4) * 16));
                ldsm4(aH[sub], sb + off);
                ldsm4(aL[sub], sb + 8192 + off);
            }
            uint32_t offb[4];
            #pragma unroll
            for (int p = 0; p < 4; p++) {
                offb[p] = swz64((uint32_t)(
                    (n0w + p * 16 + (lane & 7) + ((lane >> 4) << 3)) * 64 +
                    s * 32 + ((lane >> 3) & 1) * 16));
                ldsm4(bb[p], sb + 16384 + offb[p]);
            }
            #pragma unroll
            for (int sub = 0; sub < 2; sub++)
                #pragma unroll
                for (int p = 0; p < 4; p++) {
                    mma16816(acc[sub][p * 2 + 0], aH[sub], &bb[p][0]);
                    mma16816(acc[sub][p * 2 + 1], aH[sub], &bb[p][2]);
                }
            #pragma unroll
            for (int sub = 0; sub < 2; sub++)
                #pragma unroll
                for (int p = 0; p < 4; p++) {
                    mma16816(acc[sub][p * 2 + 0], aL[sub], &bb[p][0]);
                    mma16816(acc[sub][p * 2 + 1], aL[sub], &bb[p][2]);
                }
            #pragma unroll
            for (int p = 0; p < 4; p++)
                ldsm4(bb[p], sb + 24576 + offb[p]);
            #pragma unroll
            for (int sub = 0; sub < 2; sub++)
                #pragma unroll
                for (int p = 0; p < 4; p++) {
                    mma16816(acc[sub][p * 2 + 0], aH[sub], &bb[p][0]);
                    mma16816(acc[sub][p * 2 + 1], aH[sub], &bb[p][2]);
                }
        }
        __syncthreads();
    }

    // ---------------- epilogue ----------------
    float al = 0.f, om = 0.f;
    if (MODE == 2) { al = *alphaPtr; om = 1.0f - al; }
    const int ccol0 = n0w + (lane & 3) * 2;
    #pragma unroll
    for (int sub = 0; sub < 2; sub++) {
        const int rbase = m0 + m0w + sub * 16 + (lane >> 2);
        #pragma unroll
        for (int f = 0; f < 8; f++) {
            const int col = ccol0 + f * 8;
            const float bx = bias[col], by = bias[col + 1];
            #pragma unroll
            for (int half = 0; half < 2; half++) {
                const int r = rbase + half * 8;
                if (r >= NN) continue;
                float vx = acc[sub][f][half * 2 + 0] + bx;
                float vy = acc[sub][f][half * 2 + 1] + by;
                if (MODE < 2) {
                    vx = fmaxf(vx, 0.f); vy = fmaxf(vy, 0.f);
                    __nv_bfloat162 h2, l2;
                    split1(vx, h2.x, l2.x); split1(vy, h2.y, l2.y);
                    *(__nv_bfloat162*)(outH + (size_t)r * C + col) = h2;
                    *(__nv_bfloat162*)(outL + (size_t)r * C + col) = l2;
                    if (MODE == 0) {
                        float2 fv = make_float2(vx, vy);
                        *(float2*)(outF + (size_t)r * C + col) = fv;
                    }
                } else {
                    const float2 xr = *(const float2*)(xres + (size_t)r * C + col);
                    float2 fv;
                    fv.x = al * vx + om * xr.x;
                    fv.y = al * vy + om * xr.y;
                    *(float2*)(outF + (size_t)r * C + col) = fv;
                }
            }
        }
    }
}

// ---------------- launch ----------------
extern "C" void kernel_launch(void* const* d_in, const int* in_sizes, int n_in,
                              void* d_out, int out_size)
{
    const float* x    = (const float*)d_in[0];
    const int*   ei   = (const int*)  d_in[1];
    const float* W1l  = (const float*)d_in[2];
    const float* b1   = (const float*)d_in[3];
    const float* W1r  = (const float*)d_in[4];
    const float* W2l  = (const float*)d_in[5];
    const float* b2   = (const float*)d_in[6];
    const float* W2r  = (const float*)d_in[7];
    const float* Wd   = (const float*)d_in[8];
    const float* bd   = (const float*)d_in[9];
    const float* alph = (const float*)d_in[10];
    float* out = (float*)d_out;

    const int* src = ei;
    const int* dst = ei + NE;

    float *h1f;
    __nv_bfloat16 *xh, *xl, *aggh, *aggl, *h1h, *h1l, *h2h, *h2l;
    __nv_bfloat16 *w1h, *w1l, *w2h, *w2l, *wdh, *wdl;
    cudaGetSymbolAddress((void**)&h1f,  g_h1f);
    cudaGetSymbolAddress((void**)&xh,   g_xh);
    cudaGetSymbolAddress((void**)&xl,   g_xl);
    cudaGetSymbolAddress((void**)&aggh, g_aggh);
    cudaGetSymbolAddress((void**)&aggl, g_aggl);
    cudaGetSymbolAddress((void**)&h1h,  g_h1h);
    cudaGetSymbolAddress((void**)&h1l,  g_h1l);
    cudaGetSymbolAddress((void**)&h2h,  g_h2h);
    cudaGetSymbolAddress((void**)&h2l,  g_h2l);
    cudaGetSymbolAddress((void**)&w1h,  g_w1h);
    cudaGetSymbolAddress((void**)&w1l,  g_w1l);
    cudaGetSymbolAddress((void**)&w2h,  g_w2h);
    cudaGetSymbolAddress((void**)&w2l,  g_w2l);
    cudaGetSymbolAddress((void**)&wdh,  g_wdh);
    cudaGetSymbolAddress((void**)&wdl,  g_wdl);

    const int SMEM_GEMM = 2 * 32768;  // 64KB
    cudaFuncSetAttribute(gemm_mma_kernel<0>, cudaFuncAttributeMaxDynamicSharedMemorySize, SMEM_GEMM);
    cudaFuncSetAttribute(gemm_mma_kernel<1>, cudaFuncAttributeMaxDynamicSharedMemorySize, SMEM_GEMM);
    cudaFuncSetAttribute(gemm_mma_kernel<2>, cudaFuncAttributeMaxDynamicSharedMemorySize, SMEM_GEMM);

    const int TB = 256;
    const int gN  = (NN + TB - 1) / TB;
    const int gE  = (NE + TB - 1) / TB;
    const int gAg = (NN * 32 + TB - 1) / TB;
    const int gM  = (NN + 127) / 128;        // 782
    const int gS  = (NN * C / 4 + TB - 1) / TB;

    // independent prep
    split_kernel<<<gS, TB>>>(x, xh, xl);
    wprep_kernel<<<dim3(128, 3), 256>>>(W1l, W1r, W2l, W2r, Wd);

    // CSR build
    zero_deg_kernel<<<gN, TB>>>();
    count_kernel<<<gE, TB>>>(dst);
    scan1_kernel<<<NB_SCAN, 1024>>>();
    scan2_kernel<<<1, 128>>>();
    scan3_kernel<<<NB_SCAN, 1024>>>();
    build_kernel<<<gE, TB>>>(src, dst);

    // layer 1
    agg_kernel<<<gAg, TB>>>(x);
    gemm_mma_kernel<0><<<gM, 256, SMEM_GEMM>>>(aggh, aggl, xh, xl, w1h, w1l,
                                               b1, nullptr, nullptr, h1f, h1h, h1l);
    // layer 2
    agg_kernel<<<gAg, TB>>>(h1f);
    gemm_mma_kernel<1><<<gM, 256, SMEM_GEMM>>>(aggh, aggl, h1h, h1l, w2h, w2l,
                                               b2, nullptr, nullptr, nullptr, h2h, h2l);
    // decoder + residual blend
    gemm_mma_kernel<2><<<gM, 256, SMEM_GEMM>>>(h2h, h2l, nullptr, nullptr, wdh, wdl,
                                               bd, x, alph, out, nullptr, nullptr);

    (void)in_sizes; (void)n_in; (void)out_size;
}

// round 5
// speedup vs baseline: 1.8664x; 1.0245x over previous
#include <cuda_runtime.h>
#include <cuda_bf16.h>
#include <cstdint>
#include <cstddef>

#define NN 100000
#define NPAD 100096   // 782 * 128
#define NE 1600000
#define C 128
#define NB_SCAN 98    // ceil(NN / 1024)

// ---------------- scratch (device globals) ----------------
__device__ int   g_deg[NN];
__device__ int   g_ptr[NN + 1];
__device__ int   g_cursor[NN];
__device__ float g_invc[NN];
__device__ int   g_csr[NE];
__device__ int   g_bsum[128];
__device__ float g_h1f[(size_t)NN * C];
__device__ float g_p1 [(size_t)NPAD * C];
__device__ float g_p2 [(size_t)NPAD * C];

__device__ __nv_bfloat16 g_xh [(size_t)NPAD * C];
__device__ __nv_bfloat16 g_xl [(size_t)NPAD * C];
__device__ __nv_bfloat16 g_aggh[(size_t)NPAD * C];
__device__ __nv_bfloat16 g_aggl[(size_t)NPAD * C];
__device__ __nv_bfloat16 g_h1h[(size_t)NPAD * C];
__device__ __nv_bfloat16 g_h1l[(size_t)NPAD * C];
__device__ __nv_bfloat16 g_h2h[(size_t)NPAD * C];
__device__ __nv_bfloat16 g_h2l[(size_t)NPAD * C];

// weights: 5 pairs (wl1, wr1, wl2, wr2, wd), each [n=128][k=128], hi+lo
__device__ __nv_bfloat16 g_wh[5][128 * 128];
__device__ __nv_bfloat16 g_wl[5][128 * 128];

// ---------------- helpers ----------------
__device__ __forceinline__ uint32_t s2u(const void* p) {
    uint32_t a;
    asm("{ .reg .u64 t; cvta.to.shared.u64 t, %1; cvt.u32.u64 %0, t; }" : "=r"(a) : "l"(p));
    return a;
}
__device__ __forceinline__ void split1(float v, __nv_bfloat16& h, __nv_bfloat16& l) {
    h = __float2bfloat16(v);
    l = __float2bfloat16(v - __bfloat162float(h));
}
__device__ __forceinline__ void ldsm4(uint32_t* r, uint32_t addr) {
    asm volatile("ldmatrix.sync.aligned.m8n8.x4.shared.b16 {%0,%1,%2,%3}, [%4];"
                 : "=r"(r[0]), "=r"(r[1]), "=r"(r[2]), "=r"(r[3]) : "r"(addr));
}
__device__ __forceinline__ void mma16816(float* d, const uint32_t* a, const uint32_t* b) {
    asm volatile(
        "mma.sync.aligned.m16n8k16.row.col.f32.bf16.bf16.f32 "
        "{%0,%1,%2,%3}, {%4,%5,%6,%7}, {%8,%9}, {%0,%1,%2,%3};"
        : "+f"(d[0]), "+f"(d[1]), "+f"(d[2]), "+f"(d[3])
        : "r"(a[0]), "r"(a[1]), "r"(a[2]), "r"(a[3]), "r"(b[0]), "r"(b[1]));
}
__device__ __forceinline__ uint32_t swz64(uint32_t off) {
    return off ^ ((off >> 3) & 0x30u);
}
__device__ __forceinline__ void cp16(uint32_t saddr, const void* gaddr) {
    asm volatile("cp.async.cg.shared.global [%0], [%1], 16;" :: "r"(saddr), "l"(gaddr));
}

// ---------------- CSR build ----------------
__global__ void zero_deg_kernel() {
    int i = blockIdx.x * blockDim.x + threadIdx.x;
    if (i < NN) g_deg[i] = 0;
}
__global__ void count_kernel(const int* __restrict__ dst) {
    int e = blockIdx.x * blockDim.x + threadIdx.x;
    if (e < NE) atomicAdd(&g_deg[dst[e]], 1);
}
__global__ void scan1_kernel() {
    __shared__ int wsum[32];
    const int lane = threadIdx.x & 31;
    const int wid  = threadIdx.x >> 5;
    int i = blockIdx.x * 1024 + threadIdx.x;
    int v = (i < NN) ? g_deg[i] : 0;
    int incl = v;
    #pragma unroll
    for (int o = 1; o < 32; o <<= 1) {
        int t = __shfl_up_sync(0xFFFFFFFFu, incl, o);
        if (lane >= o) incl += t;
    }
    if (lane == 31) wsum[wid] = incl;
    __syncthreads();
    if (wid == 0) {
        int ws = wsum[lane];
        int wi = ws;
        #pragma unroll
        for (int o = 1; o < 32; o <<= 1) {
            int t = __shfl_up_sync(0xFFFFFFFFu, wi, o);
            if (lane >= o) wi += t;
        }
        wsum[lane] = wi - ws;
    }
    __syncthreads();
    int excl = wsum[wid] + incl - v;
    if (i < NN) g_ptr[i] = excl;
    if (threadIdx.x == 1023) g_bsum[blockIdx.x] = excl + v;
}
__global__ void scan2_kernel() {
    __shared__ int ws[4];
    const int t = threadIdx.x;
    const int lane = t & 31;
    const int wid  = t >> 5;
    int v = (t < NB_SCAN) ? g_bsum[t] : 0;
    int incl = v;
    #pragma unroll
    for (int o = 1; o < 32; o <<= 1) {
        int s = __shfl_up_sync(0xFFFFFFFFu, incl, o);
        if (lane >= o) incl += s;
    }
    if (lane == 31) ws[wid] = incl;
    __syncthreads();
    int add = 0;
    #pragma unroll
    for (int w = 0; w < 4; w++) if (w < wid) add += ws[w];
    int excl = add + incl - v;
    __syncthreads();
    if (t < NB_SCAN) g_bsum[t] = excl;
}
__global__ void scan3_kernel() {
    int i = blockIdx.x * 1024 + threadIdx.x;
    if (i == 0) g_ptr[NN] = NE;
    if (i < NN) {
        g_ptr[i] += g_bsum[blockIdx.x];
        int d = g_deg[i];
        g_invc[i] = 1.0f / (float)(d < 1 ? 1 : d);
        g_cursor[i] = 0;
    }
}
__global__ void build_kernel(const int* __restrict__ src, const int* __restrict__ dst) {
    int e = blockIdx.x * blockDim.x + threadIdx.x;
    if (e < NE) {
        int d   = dst[e];
        int pos = atomicAdd(&g_cursor[d], 1);
        g_csr[g_ptr[d] + pos] = src[e];
    }
}

// ---------------- fp32 -> (hi, lo) bf16 split for x ----------------
__global__ void split_kernel(const float* __restrict__ in,
                             __nv_bfloat16* __restrict__ hi,
                             __nv_bfloat16* __restrict__ lo) {
    int i = blockIdx.x * blockDim.x + threadIdx.x;
    if (i < NN * C / 4) {
        float4 v = ((const float4*)in)[i];
        __nv_bfloat162 h01, h23, l01, l23;
        split1(v.x, h01.x, l01.x); split1(v.y, h01.y, l01.y);
        split1(v.z, h23.x, l23.x); split1(v.w, h23.y, l23.y);
        ((__nv_bfloat162*)hi)[i * 2]     = h01;
        ((__nv_bfloat162*)hi)[i * 2 + 1] = h23;
        ((__nv_bfloat162*)lo)[i * 2]     = l01;
        ((__nv_bfloat162*)lo)[i * 2 + 1] = l23;
    }
}

// ---------------- weight prep: 5 pairs, grid (128, 5) ----------------
__global__ void wprep_kernel(const float* __restrict__ W1l, const float* __restrict__ W1r,
                             const float* __restrict__ W2l, const float* __restrict__ W2r,
                             const float* __restrict__ Wd) {
    const int n = blockIdx.x;
    const int which = blockIdx.y;
    const float* W =
        (which == 0) ? W1l : (which == 1) ? W1r :
        (which == 2) ? W2l : (which == 3) ? W2r : Wd;
    for (int k = threadIdx.x; k < 128; k += blockDim.x) {
        float v = W[k * C + n];
        __nv_bfloat16 h, l;
        split1(v, h, l);
        g_wh[which][n * 128 + k] = h;
        g_wl[which][n * 128 + k] = l;
    }
}

// ---------------- aggregation: warp per node ----------------
__global__ void agg_kernel(const float* __restrict__ feat) {
    int gw = (blockIdx.x * blockDim.x + threadIdx.x) >> 5;
    if (gw >= NN) return;
    int lane = threadIdx.x & 31;
    int beg = g_ptr[gw], end = g_ptr[gw + 1];
    float4 acc = make_float4(0.f, 0.f, 0.f, 0.f);
    int e = beg;
    for (; e + 4 <= end; e += 4) {
        int s0 = g_csr[e], s1 = g_csr[e + 1], s2 = g_csr[e + 2], s3 = g_csr[e + 3];
        float4 v0 = *reinterpret_cast<const float4*>(feat + (size_t)s0 * C + lane * 4);
        float4 v1 = *reinterpret_cast<const float4*>(feat + (size_t)s1 * C + lane * 4);
        float4 v2 = *reinterpret_cast<const float4*>(feat + (size_t)s2 * C + lane * 4);
        float4 v3 = *reinterpret_cast<const float4*>(feat + (size_t)s3 * C + lane * 4);
        acc.x += v0.x + v1.x + v2.x + v3.x;
        acc.y += v0.y + v1.y + v2.y + v3.y;
        acc.z += v0.z + v1.z + v2.z + v3.z;
        acc.w += v0.w + v1.w + v2.w + v3.w;
    }
    for (; e < end; e++) {
        int s = g_csr[e];
        float4 v = *reinterpret_cast<const float4*>(feat + (size_t)s * C + lane * 4);
        acc.x += v.x; acc.y += v.y; acc.z += v.z; acc.w += v.w;
    }
    float iv = g_invc[gw];
    acc.x *= iv; acc.y *= iv; acc.z *= iv; acc.w *= iv;
    __nv_bfloat162 h01, h23, l01, l23;
    split1(acc.x, h01.x, l01.x); split1(acc.y, h01.y, l01.y);
    split1(acc.z, h23.x, l23.x); split1(acc.w, h23.y, l23.y);
    size_t off = (size_t)gw * C + lane * 4;
    ((__nv_bfloat162*)(g_aggh + off))[0] = h01;
    ((__nv_bfloat162*)(g_aggh + off))[1] = h23;
    ((__nv_bfloat162*)(g_aggl + off))[0] = l01;
    ((__nv_bfloat162*)(g_aggl + off))[1] = l23;
}

// ---------------- cp.async-pipelined split-bf16 GEMM (K=128) ----------------
// D[128,128] = A[128,128] @ B^T via (AhBh + AhBl + AlBh), fp32 accum.
// MODE 0: R-branch  -> outF = acc                      (no bias)
// MODE 1: L layer1  -> relu(acc + P + bias) -> f32 + hi/lo
// MODE 2: L layer2  -> relu(acc + P + bias) -> hi/lo
// MODE 3: decoder   -> alpha*(acc + bias) + (1-alpha)*xres -> f32
template <int MODE>
__global__ __launch_bounds__(256) void gemm_mma_kernel(
    const __nv_bfloat16* __restrict__ Ah, const __nv_bfloat16* __restrict__ Al,
    const __nv_bfloat16* __restrict__ Bh, const __nv_bfloat16* __restrict__ Bl,
    const float* __restrict__ P, const float* __restrict__ bias,
    const float* __restrict__ xres, const float* __restrict__ alphaPtr,
    float* __restrict__ outF,
    __nv_bfloat16* __restrict__ outH, __nv_bfloat16* __restrict__ outL)
{
    constexpr int NCH = 4;
    extern __shared__ __align__(128) char smem[];
    const uint32_t us = s2u(smem);

    const int tid  = threadIdx.x;
    const int wid  = tid >> 5;
    const int lane = tid & 31;
    const int m0   = blockIdx.x * 128;
    const int m0w  = (wid >> 1) * 32;
    const int n0w  = (wid & 1) * 64;

    const int lrow = tid >> 1;
    const int c16a = (tid & 1) * 2;

    float acc[2][8][4];
    #pragma unroll
    for (int i = 0; i < 2; i++)
        #pragma unroll
        for (int j = 0; j < 8; j++)
            #pragma unroll
            for (int q = 0; q < 4; q++) acc[i][j][q] = 0.f;

    auto issue = [&](int kc, int buf) {
        const char* pAh = (const char*)Ah + (size_t)(m0 + lrow) * 256 + kc * 64;
        const char* pAl = (const char*)Al + (size_t)(m0 + lrow) * 256 + kc * 64;
        const char* pBh = (const char*)Bh + (size_t)lrow * 256 + kc * 64;
        const char* pBl = (const char*)Bl + (size_t)lrow * 256 + kc * 64;
        const uint32_t sb = us + buf * 32768;
        #pragma unroll
        for (int j = 0; j < 2; j++) {
            const int c16 = c16a + j;
            const uint32_t so = swz64((uint32_t)(lrow * 64 + c16 * 16));
            cp16(sb + so,          pAh + c16 * 16);
            cp16(sb + 8192 + so,   pAl + c16 * 16);
            cp16(sb + 16384 + so,  pBh + c16 * 16);
            cp16(sb + 24576 + so,  pBl + c16 * 16);
        }
        asm volatile("cp.async.commit_group;" ::: "memory");
    };

    issue(0, 0);
    for (int kc = 0; kc < NCH; kc++) {
        if (kc + 1 < NCH) {
            issue(kc + 1, (kc + 1) & 1);
            asm volatile("cp.async.wait_group 1;" ::: "memory");
        } else {
            asm volatile("cp.async.wait_group 0;" ::: "memory");
        }
        __syncthreads();
        const uint32_t sb = us + (kc & 1) * 32768;
        #pragma unroll
        for (int s = 0; s < 2; s++) {
            uint32_t aH[2][4], aL[2][4], bb[4][4];
            #pragma unroll
            for (int sub = 0; sub < 2; sub++) {
                const uint32_t off = swz64((uint32_t)(
                    (m0w + sub * 16 + (lane & 15)) * 64 + s * 32 + (lane >> 4) * 16));
                ldsm4(aH[sub], sb + off);
                ldsm4(aL[sub], sb + 8192 + off);
            }
            uint32_t offb[4];
            #pragma unroll
            for (int p = 0; p < 4; p++) {
                offb[p] = swz64((uint32_t)(
                    (n0w + p * 16 + (lane & 7) + ((lane >> 4) << 3)) * 64 +
                    s * 32 + ((lane >> 3) & 1) * 16));
                ldsm4(bb[p], sb + 16384 + offb[p]);
            }
            #pragma unroll
            for (int sub = 0; sub < 2; sub++)
                #pragma unroll
                for (int p = 0; p < 4; p++) {
                    mma16816(acc[sub][p * 2 + 0], aH[sub], &bb[p][0]);
                    mma16816(acc[sub][p * 2 + 1], aH[sub], &bb[p][2]);
                }
            #pragma unroll
            for (int sub = 0; sub < 2; sub++)
                #pragma unroll
                for (int p = 0; p < 4; p++) {
                    mma16816(acc[sub][p * 2 + 0], aL[sub], &bb[p][0]);
                    mma16816(acc[sub][p * 2 + 1], aL[sub], &bb[p][2]);
                }
            #pragma unroll
            for (int p = 0; p < 4; p++)
                ldsm4(bb[p], sb + 24576 + offb[p]);
            #pragma unroll
            for (int sub = 0; sub < 2; sub++)
                #pragma unroll
                for (int p = 0; p < 4; p++) {
                    mma16816(acc[sub][p * 2 + 0], aH[sub], &bb[p][0]);
                    mma16816(acc[sub][p * 2 + 1], aH[sub], &bb[p][2]);
                }
        }
        __syncthreads();
    }

    // ---------------- epilogue ----------------
    float al = 0.f, om = 0.f;
    if (MODE == 3) { al = *alphaPtr; om = 1.0f - al; }
    const int ccol0 = n0w + (lane & 3) * 2;
    #pragma unroll
    for (int sub = 0; sub < 2; sub++) {
        const int rbase = m0 + m0w + sub * 16 + (lane >> 2);
        #pragma unroll
        for (int f = 0; f < 8; f++) {
            const int col = ccol0 + f * 8;
            float bx = 0.f, by = 0.f;
            if (MODE != 0) { bx = bias[col]; by = bias[col + 1]; }
            #pragma unroll
            for (int half = 0; half < 2; half++) {
                const int r = rbase + half * 8;
                if (r >= NN) continue;
                float vx = acc[sub][f][half * 2 + 0] + bx;
                float vy = acc[sub][f][half * 2 + 1] + by;
                if (MODE == 0) {
                    *(float2*)(outF + (size_t)r * C + col) = make_float2(vx, vy);
                } else if (MODE == 1 || MODE == 2) {
                    const float2 pv = *(const float2*)(P + (size_t)r * C + col);
                    vx = fmaxf(vx + pv.x, 0.f);
                    vy = fmaxf(vy + pv.y, 0.f);
                    __nv_bfloat162 h2, l2;
                    split1(vx, h2.x, l2.x); split1(vy, h2.y, l2.y);
                    *(__nv_bfloat162*)(outH + (size_t)r * C + col) = h2;
                    *(__nv_bfloat162*)(outL + (size_t)r * C + col) = l2;
                    if (MODE == 1)
                        *(float2*)(outF + (size_t)r * C + col) = make_float2(vx, vy);
                } else {
                    const float2 xr = *(const float2*)(xres + (size_t)r * C + col);
                    float2 fv;
                    fv.x = al * vx + om * xr.x;
                    fv.y = al * vy + om * xr.y;
                    *(float2*)(outF + (size_t)r * C + col) = fv;
                }
            }
        }
    }
}

// ---------------- launch ----------------
extern "C" void kernel_launch(void* const* d_in, const int* in_sizes, int n_in,
                              void* d_out, int out_size)
{
    const float* x    = (const float*)d_in[0];
    const int*   ei   = (const int*)  d_in[1];
    const float* W1l  = (const float*)d_in[2];
    const float* b1   = (const float*)d_in[3];
    const float* W1r  = (const float*)d_in[4];
    const float* W2l  = (const float*)d_in[5];
    const float* b2   = (const float*)d_in[6];
    const float* W2r  = (const float*)d_in[7];
    const float* Wd   = (const float*)d_in[8];
    const float* bd   = (const float*)d_in[9];
    const float* alph = (const float*)d_in[10];
    float* out = (float*)d_out;

    const int* src = ei;
    const int* dst = ei + NE;

    float *h1f, *p1, *p2;
    __nv_bfloat16 *xh, *xl, *aggh, *aggl, *h1h, *h1l, *h2h, *h2l;
    cudaGetSymbolAddress((void**)&h1f,  g_h1f);
    cudaGetSymbolAddress((void**)&p1,   g_p1);
    cudaGetSymbolAddress((void**)&p2,   g_p2);
    cudaGetSymbolAddress((void**)&xh,   g_xh);
    cudaGetSymbolAddress((void**)&xl,   g_xl);
    cudaGetSymbolAddress((void**)&aggh, g_aggh);
    cudaGetSymbolAddress((void**)&aggl, g_aggl);
    cudaGetSymbolAddress((void**)&h1h,  g_h1h);
    cudaGetSymbolAddress((void**)&h1l,  g_h1l);
    cudaGetSymbolAddress((void**)&h2h,  g_h2h);
    cudaGetSymbolAddress((void**)&h2l,  g_h2l);
    __nv_bfloat16 *wh0, *wl0;
    cudaGetSymbolAddress((void**)&wh0, g_wh);
    cudaGetSymbolAddress((void**)&wl0, g_wl);
    auto WH = [&](int i) { return wh0 + (size_t)i * 128 * 128; };
    auto WL = [&](int i) { return wl0 + (size_t)i * 128 * 128; };

    static cudaStream_t s1 = nullptr;
    static cudaEvent_t ev0 = nullptr, evR1 = nullptr, evL1 = nullptr, evR2 = nullptr;
    if (s1 == nullptr) {
        cudaStreamCreateWithFlags(&s1, cudaStreamNonBlocking);
        cudaEventCreateWithFlags(&ev0,  cudaEventDisableTiming);
        cudaEventCreateWithFlags(&evR1, cudaEventDisableTiming);
        cudaEventCreateWithFlags(&evL1, cudaEventDisableTiming);
        cudaEventCreateWithFlags(&evR2, cudaEventDisableTiming);
    }

    const int SMEM_GEMM = 2 * 32768;
    static bool attrSet = false;
    if (!attrSet) {
        cudaFuncSetAttribute(gemm_mma_kernel<0>, cudaFuncAttributeMaxDynamicSharedMemorySize, SMEM_GEMM);
        cudaFuncSetAttribute(gemm_mma_kernel<1>, cudaFuncAttributeMaxDynamicSharedMemorySize, SMEM_GEMM);
        cudaFuncSetAttribute(gemm_mma_kernel<2>, cudaFuncAttributeMaxDynamicSharedMemorySize, SMEM_GEMM);
        cudaFuncSetAttribute(gemm_mma_kernel<3>, cudaFuncAttributeMaxDynamicSharedMemorySize, SMEM_GEMM);
        attrSet = true;
    }

    const int TB = 256;
    const int gN  = (NN + TB - 1) / TB;
    const int gE  = (NE + TB - 1) / TB;
    const int gAg = (NN * 32 + TB - 1) / TB;
    const int gM  = (NN + 127) / 128;
    const int gS  = (NN * C / 4 + TB - 1) / TB;
    const cudaStream_t s0 = (cudaStream_t)0;   // legacy default (capture) stream

    // fork side stream
    cudaEventRecord(ev0, s0);
    cudaStreamWaitEvent(s1, ev0, 0);

    // s1: prep + R-branch of layer 1  (independent of graph structure)
    split_kernel<<<gS, TB, 0, s1>>>(x, xh, xl);
    wprep_kernel<<<dim3(128, 5), 256, 0, s1>>>(W1l, W1r, W2l, W2r, Wd);
    gemm_mma_kernel<0><<<gM, 256, SMEM_GEMM, s1>>>(xh, xl, WH(1), WL(1),
                                                   nullptr, nullptr, nullptr, nullptr,
                                                   p1, nullptr, nullptr);
    cudaEventRecord(evR1, s1);

    // s0: CSR build + aggregation layer 1
    zero_deg_kernel<<<gN, TB, 0, s0>>>();
    count_kernel<<<gE, TB, 0, s0>>>(dst);
    scan1_kernel<<<NB_SCAN, 1024, 0, s0>>>();
    scan2_kernel<<<1, 128, 0, s0>>>();
    scan3_kernel<<<NB_SCAN, 1024, 0, s0>>>();
    build_kernel<<<gE, TB, 0, s0>>>(src, dst);
    agg_kernel<<<gAg, TB, 0, s0>>>(x);

    // join R1, then L-branch layer 1
    cudaStreamWaitEvent(s0, evR1, 0);
    gemm_mma_kernel<1><<<gM, 256, SMEM_GEMM, s0>>>(aggh, aggl, WH(0), WL(0),
                                                   p1, b1, nullptr, nullptr,
                                                   h1f, h1h, h1l);
    cudaEventRecord(evL1, s0);

    // s1: R-branch layer 2 (needs h1 hi/lo) — overlaps agg2
    cudaStreamWaitEvent(s1, evL1, 0);
    gemm_mma_kernel<0><<<gM, 256, SMEM_GEMM, s1>>>(h1h, h1l, WH(3), WL(3),
                                                   nullptr, nullptr, nullptr, nullptr,
                                                   p2, nullptr, nullptr);
    cudaEventRecord(evR2, s1);

    // s0: aggregation layer 2
    agg_kernel<<<gAg, TB, 0, s0>>>(h1f);

    // join R2, then L-branch layer 2 + decoder
    cudaStreamWaitEvent(s0, evR2, 0);
    gemm_mma_kernel<2><<<gM, 256, SMEM_GEMM, s0>>>(aggh, aggl, WH(2), WL(2),
                                                   p2, b2, nullptr, nullptr,
                                                   nullptr, h2h, h2l);
    gemm_mma_kernel<3><<<gM, 256, SMEM_GEMM, s0>>>(h2h, h2l, WH(4), WL(4),
                                                   nullptr, bd, x, alph,
                                                   out, nullptr, nullptr);

    (void)in_sizes; (void)n_in; (void)out_size;
}